// round 1
// baseline (speedup 1.0000x reference)
#include <cuda_runtime.h>
#include <cstdint>

// EdgeEmbedding — collapsed to a pure per-edge elementwise kernel.
//
// Key identities (see analysis):
//   counts == 2 exactly; (a+a)/2 == a exactly  => pair_vec == edge_vec*orient per edge
//   SH parity cancels orientation              => edge_attr = SH_l2(edge_vec / r)
//   |edge_vec*orient| == |edge_vec|            => edge_length = |edge_vec|
// So edge_to_pair / edge_is_reversed / num_pairs are not needed.

#define SQRT3f  1.7320508075688772f
#define SQRT15f 3.8729833462074170f
#define SQRT5f  2.2360679774997896f
#define SQRT_2_OVER_RC 0.6324555320336759f   // sqrt(2/5)
#define PI_OVER_RC     0.6283185307179586f   // pi/5

__global__ void __launch_bounds__(256)
edge_embedding_kernel(const float* __restrict__ ev,
                      float* __restrict__ out_len,
                      float* __restrict__ out_emb,
                      float* __restrict__ out_attr,
                      int E)
{
    int e = blockIdx.x * blockDim.x + threadIdx.x;
    if (e >= E) return;

    const float x = ev[3 * e + 0];
    const float y = ev[3 * e + 1];
    const float z = ev[3 * e + 2];

    const float r    = sqrtf(x * x + y * y + z * z);
    const float rinv = 1.0f / fmaxf(r, 1e-12f);

    out_len[e] = r;

    // ---- polynomial cutoff: p=6 -> env = 1 - 28 x^6 + 48 x^7 - 21 x^8 ----
    const float xr = r / 5.0f;
    float env = 0.0f;
    if (xr < 1.0f) {
        const float x2 = xr * xr;
        const float x6 = x2 * x2 * x2;
        env = 1.0f + x6 * (-28.0f + xr * (48.0f - 21.0f * xr));
    }

    // ---- Bessel basis: sqrt(2/RC) * sin(k*pi*r/RC) / r_safe, k = 1..8 ----
    // Chebyshev recurrence: sin((k+1)t) = 2cos(t) sin(kt) - sin((k-1)t)
    const float theta = PI_OVER_RC * r;
    float s1, c1;
    sincosf(theta, &s1, &c1);
    const float pref = SQRT_2_OVER_RC * rinv * env;
    const float tw   = 2.0f * c1;

    float emb[8];
    float sk_m1 = 0.0f, sk = s1;
#pragma unroll
    for (int k = 0; k < 8; ++k) {
        emb[k] = pref * sk;
        const float sk_p1 = tw * sk - sk_m1;
        sk_m1 = sk;
        sk = sk_p1;
    }

    // embedding rows are 32B-aligned (8 floats * 4B * e) -> two STG.128
    float4* embv = reinterpret_cast<float4*>(out_emb);
    embv[2 * e + 0] = make_float4(emb[0], emb[1], emb[2], emb[3]);
    embv[2 * e + 1] = make_float4(emb[4], emb[5], emb[6], emb[7]);

    // ---- spherical harmonics l<=2 on u = edge_vec / r ----
    const float ux = x * rinv, uy = y * rinv, uz = z * rinv;
    float* a = out_attr + 9ll * e;
    a[0] = 1.0f;
    a[1] = SQRT3f * ux;
    a[2] = SQRT3f * uy;
    a[3] = SQRT3f * uz;
    a[4] = SQRT15f * ux * uy;
    a[5] = SQRT15f * uy * uz;
    a[6] = 0.5f * SQRT5f * (3.0f * uz * uz - 1.0f);
    a[7] = SQRT15f * ux * uz;
    a[8] = 0.5f * SQRT15f * (ux * ux - uy * uy);
}

extern "C" void kernel_launch(void* const* d_in, const int* in_sizes, int n_in,
                              void* d_out, int out_size)
{
    const float* ev = (const float*)d_in[0];
    const int E = in_sizes[0] / 3;          // 3,000,000 edges

    float* out      = (float*)d_out;
    float* out_len  = out;                  // [E]
    float* out_emb  = out + (size_t)E;      // [E, 8]
    float* out_attr = out + (size_t)9 * E;  // [E, 9]

    const int threads = 256;
    const int blocks  = (E + threads - 1) / threads;
    edge_embedding_kernel<<<blocks, threads>>>(ev, out_len, out_emb, out_attr, E);
}

// round 2
// speedup vs baseline: 2.4297x; 2.4297x over previous
#include <cuda_runtime.h>
#include <cstdint>

// EdgeEmbedding — per-edge elementwise (pipeline algebraically collapsed; see R1),
// now with smem-staged fully-coalesced float4 global I/O.
//
// Identities: counts==2 exactly, (a+a)/2==a  => pair_vec == edge_vec*orient per edge;
// SH parity cancels orientation              => edge_attr = SH_l2(edge_vec/r);
// norm is orientation-invariant              => edge_length = |edge_vec|.

#define SQRT3f  1.7320508075688772f
#define SQRT15f 3.8729833462074170f
#define SQRT5f  2.2360679774997896f
#define SQRT_2_OVER_RC 0.6324555320336759f   // sqrt(2/5)
#define PI_OVER_RC     0.6283185307179586f   // pi/5

#define TILE 256

__global__ void __launch_bounds__(TILE)
edge_embedding_kernel(const float* __restrict__ ev,
                      float* __restrict__ out,   // [E | E*8 | E*9]
                      int E)
{
    __shared__ float  s_in[3 * TILE];        //  3 KB
    __shared__ float4 s_emb[2 * TILE];       //  8 KB (interleaved: [2e],[2e+1])
    __shared__ float  s_attr[9 * TILE];      //  9 KB

    const int t    = threadIdx.x;
    const int base = blockIdx.x * TILE;
    const int rem  = min(TILE, E - base);

    // ---- stage input: 3*rem floats, coalesced float4 ----
    {
        const int nflt = 3 * rem;
        const int n4   = nflt >> 2;
        const float4* ev4 = reinterpret_cast<const float4*>(ev + 3ll * base);
        float4* s4 = reinterpret_cast<float4*>(s_in);
        for (int k = t; k < n4; k += TILE) s4[k] = __ldcs(&ev4[k]);
        for (int k = (n4 << 2) + t; k < nflt; k += TILE) s_in[k] = __ldcs(&ev[3ll * base + k]);
    }
    __syncthreads();

    // ---- compute (one edge per thread) ----
    if (t < rem) {
        const float x = s_in[3 * t + 0];
        const float y = s_in[3 * t + 1];
        const float z = s_in[3 * t + 2];

        const float r    = sqrtf(x * x + y * y + z * z);
        const float rinv = 1.0f / fmaxf(r, 1e-12f);

        out[base + t] = r;   // coalesced STG.32, full lines

        // poly cutoff p=6: 1 - 28 x^6 + 48 x^7 - 21 x^8
        const float xr = r * 0.2f;
        float env = 0.0f;
        if (xr < 1.0f) {
            const float x2 = xr * xr;
            const float x6 = x2 * x2 * x2;
            env = 1.0f + x6 * (-28.0f + xr * (48.0f - 21.0f * xr));
        }

        // Bessel: sqrt(2/RC)*sin(k*pi*r/RC)/r * env, k=1..8 via Chebyshev recurrence
        const float theta = PI_OVER_RC * r;
        float s1, c1;
        sincosf(theta, &s1, &c1);
        const float pref = SQRT_2_OVER_RC * rinv * env;
        const float tw   = 2.0f * c1;

        float emb[8];
        float sk_m1 = 0.0f, sk = s1;
#pragma unroll
        for (int k = 0; k < 8; ++k) {
            emb[k] = pref * sk;
            const float sk_p1 = tw * sk - sk_m1;
            sk_m1 = sk;
            sk = sk_p1;
        }
        s_emb[2 * t + 0] = make_float4(emb[0], emb[1], emb[2], emb[3]);
        s_emb[2 * t + 1] = make_float4(emb[4], emb[5], emb[6], emb[7]);

        // SH l<=2 on u = v/r ; stride-9 scalar STS -> conflict-free
        const float ux = x * rinv, uy = y * rinv, uz = z * rinv;
        float* a = s_attr + 9 * t;
        a[0] = 1.0f;
        a[1] = SQRT3f * ux;
        a[2] = SQRT3f * uy;
        a[3] = SQRT3f * uz;
        a[4] = SQRT15f * ux * uy;
        a[5] = SQRT15f * uy * uz;
        a[6] = 0.5f * SQRT5f * (3.0f * uz * uz - 1.0f);
        a[7] = SQRT15f * ux * uz;
        a[8] = 0.5f * SQRT15f * (ux * ux - uy * uy);
    }
    __syncthreads();

    // ---- writeout embedding: 2*rem float4, perfectly linear ----
    {
        float4* o = reinterpret_cast<float4*>(out + (size_t)E) + 2ll * base;
        const int n4 = 2 * rem;
        for (int k = t; k < n4; k += TILE) __stcs(&o[k], s_emb[k]);
    }

    // ---- writeout attr: 9*rem floats as linear float4 (+scalar tail) ----
    {
        float* oat = out + 9ll * (size_t)E + 9ll * base;
        const int nflt = 9 * rem;
        const int n4   = nflt >> 2;
        const float4* sa4 = reinterpret_cast<const float4*>(s_attr);
        float4* o4 = reinterpret_cast<float4*>(oat);  // 9*base and 9*E floats are 16B-aligned here
        for (int k = t; k < n4; k += TILE) __stcs(&o4[k], sa4[k]);
        for (int k = (n4 << 2) + t; k < nflt; k += TILE) oat[k] = s_attr[k];
    }
}

extern "C" void kernel_launch(void* const* d_in, const int* in_sizes, int n_in,
                              void* d_out, int out_size)
{
    const float* ev = (const float*)d_in[0];
    const int E = in_sizes[0] / 3;          // 3,000,000 edges

    float* out = (float*)d_out;

    const int blocks = (E + TILE - 1) / TILE;
    edge_embedding_kernel<<<blocks, TILE>>>(ev, out, E);
}

// round 3
// speedup vs baseline: 2.8687x; 1.1807x over previous
#include <cuda_runtime.h>
#include <cstdint>

// EdgeEmbedding — per-edge elementwise (pipeline algebraically collapsed; see R1),
// smem-staged coalesced I/O; R3: unrolled main path, 2-way-conflict emb layout,
// occupancy forced to 8 blocks/SM, fast sincos.

#define SQRT3f  1.7320508075688772f
#define SQRT15f 3.8729833462074170f
#define SQRT5f  2.2360679774997896f
#define SQRT_2_OVER_RC 0.6324555320336759f   // sqrt(2/5)
#define PI_OVER_RC     0.6283185307179586f   // pi/5

#define TILE 256

__global__ void __launch_bounds__(TILE, 8)
edge_embedding_kernel(const float* __restrict__ ev,
                      float* __restrict__ out,   // [E | E*8 | E*9]
                      int E)
{
    __shared__ float  s_in[3 * TILE];        //  3 KB
    __shared__ float4 s_emb[2 * TILE];       //  8 KB ([t]=lo half of edge t, [256+t]=hi half)
    __shared__ float  s_attr[9 * TILE];      //  9 KB

    const int  t    = threadIdx.x;
    const int  base = blockIdx.x * TILE;
    const bool full = (base + TILE <= E);
    const int  rem  = full ? TILE : (E - base);

    // ---- stage input: coalesced float4 ----
    if (full) {
        if (t < (3 * TILE) / 4) {
            reinterpret_cast<float4*>(s_in)[t] =
                __ldcs(reinterpret_cast<const float4*>(ev + 3ll * base) + t);
        }
    } else {
        const int nflt = 3 * rem;
        for (int k = t; k < nflt; k += TILE) s_in[k] = __ldcs(&ev[3ll * base + k]);
    }
    __syncthreads();

    // ---- compute (one edge per thread) ----
    if (t < rem) {
        const float x = s_in[3 * t + 0];
        const float y = s_in[3 * t + 1];
        const float z = s_in[3 * t + 2];

        const float r    = sqrtf(x * x + y * y + z * z);
        const float rinv = 1.0f / fmaxf(r, 1e-12f);

        out[base + t] = r;   // coalesced full-sector STG.32

        // poly cutoff p=6: 1 - 28 x^6 + 48 x^7 - 21 x^8
        const float xr = r * 0.2f;
        float env = 0.0f;
        if (xr < 1.0f) {
            const float x2 = xr * xr;
            const float x6 = x2 * x2 * x2;
            env = 1.0f + x6 * (-28.0f + xr * (48.0f - 21.0f * xr));
        }

        // Bessel: sqrt(2/RC)*sin(k*pi*r/RC)/r * env, k=1..8 (Chebyshev recurrence)
        const float theta = PI_OVER_RC * r;
        float s1, c1;
        __sincosf(theta, &s1, &c1);
        const float pref = SQRT_2_OVER_RC * rinv * env;
        const float tw   = 2.0f * c1;

        float emb[8];
        float sk_m1 = 0.0f, sk = s1;
#pragma unroll
        for (int k = 0; k < 8; ++k) {
            emb[k] = pref * sk;
            const float sk_p1 = tw * sk - sk_m1;
            sk_m1 = sk;
            sk = sk_p1;
        }
        s_emb[t]        = make_float4(emb[0], emb[1], emb[2], emb[3]);
        s_emb[TILE + t] = make_float4(emb[4], emb[5], emb[6], emb[7]);

        // SH l<=2 on u = v/r ; stride-9 scalar STS -> conflict-free
        const float ux = x * rinv, uy = y * rinv, uz = z * rinv;
        float* a = s_attr + 9 * t;
        a[0] = 1.0f;
        a[1] = SQRT3f * ux;
        a[2] = SQRT3f * uy;
        a[3] = SQRT3f * uz;
        a[4] = SQRT15f * ux * uy;
        a[5] = SQRT15f * uy * uz;
        a[6] = 0.5f * SQRT5f * (3.0f * uz * uz - 1.0f);
        a[7] = SQRT15f * ux * uz;
        a[8] = 0.5f * SQRT15f * (ux * ux - uy * uy);
    }
    __syncthreads();

    // ---- writeout ----
    float4*       oe  = reinterpret_cast<float4*>(out + (size_t)E) + 2ll * base;
    float4*       oa  = reinterpret_cast<float4*>(out + 9ll * (size_t)E) +
                        (9ll * base) / 4;            // 9*base % 4 == 0 (base mult of 256)
    const float4* sa4 = reinterpret_cast<const float4*>(s_attr);

    if (full) {
        // emb: global float4 index g -> smem index (g&1)*TILE + (g>>1)
        const int src0 = ((t & 1) << 8) + (t >> 1);
        __stcs(&oe[t],        s_emb[src0]);
        __stcs(&oe[t + 256],  s_emb[src0 + 128]);

        // attr: 9*256/4 = 576 float4, perfectly linear
        __stcs(&oa[t],        sa4[t]);
        __stcs(&oa[t + 256],  sa4[t + 256]);
        if (t < 64) __stcs(&oa[t + 512], sa4[t + 512]);
    } else {
        const int n4e = 2 * rem;
        for (int k = t; k < n4e; k += TILE)
            __stcs(&oe[k], s_emb[((k & 1) << 8) + (k >> 1)]);

        float* oat = out + 9ll * (size_t)E + 9ll * base;
        const int nflt = 9 * rem;
        const int n4   = nflt >> 2;
        for (int k = t; k < n4; k += TILE) __stcs(reinterpret_cast<float4*>(oat) + k, sa4[k]);
        for (int k = (n4 << 2) + t; k < nflt; k += TILE) oat[k] = s_attr[k];
    }
}

extern "C" void kernel_launch(void* const* d_in, const int* in_sizes, int n_in,
                              void* d_out, int out_size)
{
    const float* ev = (const float*)d_in[0];
    const int E = in_sizes[0] / 3;          // 3,000,000 edges

    float* out = (float*)d_out;

    const int blocks = (E + TILE - 1) / TILE;
    edge_embedding_kernel<<<blocks, TILE>>>(ev, out, E);
}